// round 7
// baseline (speedup 1.0000x reference)
#include <cuda_runtime.h>
#include <math.h>

#define BATCH 65536
#define IN_F  2048
#define GROUP 256
#define VEC_ROW (IN_F / 4)        // 512 float4 per row
#define KSTEPS  (VEC_ROW / 32)    // 16 float4 per lane per row
#define NSM 152
#define CHUNK 4                   // rows per work unit
#define NCHUNKS (BATCH / CHUNK)   // 16384
#define PF 2                      // prefetch distance (3-stage pipeline)
#define NGROUPS (BATCH / GROUP)   // 256
#define CHUNKS_PER_GROUP (GROUP / CHUNK)   // 64

// Zero-initialized device scratch. enc() maps every finite float to a uint
// > 0, so 0 is the max-identity; the winner's atomicExch restores 0 for the
// next run (graph replays are stream-ordered, so the reset is always visible).
__device__ unsigned g_gmax[NGROUPS];
__device__ unsigned g_gcount[NGROUPS];

// Order-preserving float<->uint encoding (finite floats only).
__device__ __forceinline__ unsigned encf(float v)
{
    unsigned u = __float_as_uint(v);
    return (v >= 0.0f) ? (u | 0x80000000u) : ~u;
}
__device__ __forceinline__ float decf(unsigned u)
{
    return (u & 0x80000000u) ? __uint_as_float(u & 0x7FFFFFFFu)
                             : __uint_as_float(~u);
}

// ---------------- Single fused kernel: GEMV + GELU + group max -------------
__global__ __launch_bounds__(1024, 1)
void gemv_fused(const float* __restrict__ x,
                const float* __restrict__ w,
                const float* __restrict__ bias,
                float* __restrict__ out)
{
    __shared__ float4 sw[VEC_ROW];   // 8 KB weight cache

    const int tid  = threadIdx.x;
    const int warp = tid >> 5;
    const int lane = tid & 31;

    if (tid < VEC_ROW) sw[tid] = reinterpret_cast<const float4*>(w)[tid];
    __syncthreads();

    const float b = bias[0];

    // Contiguous chunk span per CTA: 107 or 108 chunks (16384 over 152 CTAs).
    const int per = NCHUNKS / NSM;          // 107
    const int rem = NCHUNKS % NSM;          // 120
    const int bx  = blockIdx.x;
    const int begin = bx * per + (bx < rem ? bx : rem);
    const int count = per + (bx < rem ? 1 : 0);

    for (int ci = warp; ci < count; ci += 32) {
        const int row0 = (begin + ci) * CHUNK;
        const float4* __restrict__ xb =
            reinterpret_cast<const float4*>(x + (size_t)row0 * IN_F) + lane;

        float s0 = 0.f, s1 = 0.f, s2 = 0.f, s3 = 0.f;

        // 3-stage software pipeline: ~12 LDG.128 in flight per warp.
        float4 buf[PF + 1][4];
        #pragma unroll
        for (int p = 0; p < PF; p++) {
            const int off = p * 32;
            buf[p][0] = __ldcs(xb + off);
            buf[p][1] = __ldcs(xb + off + 1 * VEC_ROW);
            buf[p][2] = __ldcs(xb + off + 2 * VEC_ROW);
            buf[p][3] = __ldcs(xb + off + 3 * VEC_ROW);
        }

        #pragma unroll
        for (int i = 0; i < KSTEPS; i++) {
            if (i + PF < KSTEPS) {
                const int off = (i + PF) * 32;
                const int st  = (i + PF) % (PF + 1);
                buf[st][0] = __ldcs(xb + off);
                buf[st][1] = __ldcs(xb + off + 1 * VEC_ROW);
                buf[st][2] = __ldcs(xb + off + 2 * VEC_ROW);
                buf[st][3] = __ldcs(xb + off + 3 * VEC_ROW);
            }
            const int cu = i % (PF + 1);
            float4 wv = sw[lane + i * 32];
            s0 = fmaf(buf[cu][0].x, wv.x, s0); s0 = fmaf(buf[cu][0].y, wv.y, s0);
            s0 = fmaf(buf[cu][0].z, wv.z, s0); s0 = fmaf(buf[cu][0].w, wv.w, s0);
            s1 = fmaf(buf[cu][1].x, wv.x, s1); s1 = fmaf(buf[cu][1].y, wv.y, s1);
            s1 = fmaf(buf[cu][1].z, wv.z, s1); s1 = fmaf(buf[cu][1].w, wv.w, s1);
            s2 = fmaf(buf[cu][2].x, wv.x, s2); s2 = fmaf(buf[cu][2].y, wv.y, s2);
            s2 = fmaf(buf[cu][2].z, wv.z, s2); s2 = fmaf(buf[cu][2].w, wv.w, s2);
            s3 = fmaf(buf[cu][3].x, wv.x, s3); s3 = fmaf(buf[cu][3].y, wv.y, s3);
            s3 = fmaf(buf[cu][3].z, wv.z, s3); s3 = fmaf(buf[cu][3].w, wv.w, s3);
        }

        // 4 interleaved butterfly all-reduces.
        #pragma unroll
        for (int o = 16; o > 0; o >>= 1) {
            s0 += __shfl_xor_sync(0xFFFFFFFFu, s0, o);
            s1 += __shfl_xor_sync(0xFFFFFFFFu, s1, o);
            s2 += __shfl_xor_sync(0xFFFFFFFFu, s2, o);
            s3 += __shfl_xor_sync(0xFFFFFFFFu, s3, o);
        }

        // Epilogue: lanes 0..3 compute the 4 row GELUs; zero-fill non-head
        // rows (head rows are written only by the group winner below).
        float v = -INFINITY;
        if (lane < 4) {
            float sum = (lane == 0) ? s0 : (lane == 1) ? s1 : (lane == 2) ? s2 : s3;
            float p = (sum + b) * 0.25f;
            float inner = 0.7978845608f * (p + 0.044715f * p * p * p);
            float g = 0.5f * p * (1.0f + tanhf(inner));
            v = g * 2.0f;
            const bool isHead = ((row0 & (GROUP - 1)) == 0) && (lane == 0);
            if (!isHead) out[row0 + lane] = 0.0f;
        }
        v = fmaxf(v, __shfl_xor_sync(0xFFFFFFFFu, v, 1));
        v = fmaxf(v, __shfl_xor_sync(0xFFFFFFFFu, v, 2));

        if (lane == 0) {
            const int g = row0 >> 8;                 // row0 / GROUP
            atomicMax(&g_gmax[g], encf(v));
            __threadfence();                          // max visible before count
            unsigned old = atomicAdd(&g_gcount[g], 1u);
            if (old == CHUNKS_PER_GROUP - 1) {        // 64th (last) arriver
                __threadfence();                      // see all prior maxes
                unsigned m = atomicExch(&g_gmax[g], 0u);  // read + reset identity
                g_gcount[g] = 0u;                     // reset for next replay
                out[row0 & ~(GROUP - 1)] = decf(m);
            }
        }
    }
}

extern "C" void kernel_launch(void* const* d_in, const int* in_sizes, int n_in,
                              void* d_out, int out_size)
{
    const float* x    = (const float*)d_in[0];   // [65536, 2048]
    const float* w    = (const float*)d_in[1];   // [1, 2048]
    const float* bias = (const float*)d_in[2];   // [1]
    float* out = (float*)d_out;                  // [65536]

    gemv_fused<<<NSM, 1024>>>(x, w, bias, out);
}

// round 8
// speedup vs baseline: 1.0248x; 1.0248x over previous
#include <cuda_runtime.h>
#include <math.h>

#define BATCH 65536
#define IN_F  2048
#define GROUP 256
#define VEC_ROW (IN_F / 4)        // 512 float4 per row
#define KSTEPS  (VEC_ROW / 32)    // 16 float4 per lane per row
#define NSM 152
#define CHUNK 4                   // rows per work unit
#define NCHUNKS (BATCH / CHUNK)   // 16384
#define PF 2                      // prefetch distance (3-stage pipeline)
#define NGROUPS (BATCH / GROUP)   // 256

// float atomic max via signed/unsigned ordering trick (valid for all finite
// floats and -inf init): non-negative -> int max; negative -> uint min.
__device__ __forceinline__ void atomicMaxFloat(float* addr, float v)
{
    if (v >= 0.0f) atomicMax((int*)addr, __float_as_int(v));
    else           atomicMin((unsigned int*)addr, __float_as_uint(v));
}

// -------- Phase 0: init ONLY the 256 group heads to -inf (1 KB) ------------
__global__ __launch_bounds__(NGROUPS)
void init_heads(float* __restrict__ out)
{
    out[threadIdx.x * GROUP] = -INFINITY;
}

// ---------------- Phase 1: persistent GEMV + GELU + atomic group max -------
// Also zero-fills all non-head output rows (d_out is poisoned).
__global__ __launch_bounds__(1024, 1)
void gemv_phase1(const float* __restrict__ x,
                 const float* __restrict__ w,
                 const float* __restrict__ bias,
                 float* __restrict__ out)
{
    __shared__ float4 sw[VEC_ROW];   // 8 KB weight cache

    const int tid  = threadIdx.x;
    const int warp = tid >> 5;
    const int lane = tid & 31;

    if (tid < VEC_ROW) sw[tid] = reinterpret_cast<const float4*>(w)[tid];
    __syncthreads();

    const float b = bias[0];

    // Contiguous chunk span per CTA: 107 or 108 chunks (16384 over 152 CTAs).
    const int per = NCHUNKS / NSM;          // 107
    const int rem = NCHUNKS % NSM;          // 120
    const int bx  = blockIdx.x;
    const int begin = bx * per + (bx < rem ? bx : rem);
    const int count = per + (bx < rem ? 1 : 0);

    for (int ci = warp; ci < count; ci += 32) {
        const int row0 = (begin + ci) * CHUNK;
        const float4* __restrict__ xb =
            reinterpret_cast<const float4*>(x + (size_t)row0 * IN_F) + lane;

        float s0 = 0.f, s1 = 0.f, s2 = 0.f, s3 = 0.f;

        // 3-stage software pipeline: ~12 LDG.128 in flight per warp.
        float4 buf[PF + 1][4];
        #pragma unroll
        for (int p = 0; p < PF; p++) {
            const int off = p * 32;
            buf[p][0] = __ldcs(xb + off);
            buf[p][1] = __ldcs(xb + off + 1 * VEC_ROW);
            buf[p][2] = __ldcs(xb + off + 2 * VEC_ROW);
            buf[p][3] = __ldcs(xb + off + 3 * VEC_ROW);
        }

        #pragma unroll
        for (int i = 0; i < KSTEPS; i++) {
            if (i + PF < KSTEPS) {
                const int off = (i + PF) * 32;
                const int st  = (i + PF) % (PF + 1);
                buf[st][0] = __ldcs(xb + off);
                buf[st][1] = __ldcs(xb + off + 1 * VEC_ROW);
                buf[st][2] = __ldcs(xb + off + 2 * VEC_ROW);
                buf[st][3] = __ldcs(xb + off + 3 * VEC_ROW);
            }
            const int cu = i % (PF + 1);
            float4 wv = sw[lane + i * 32];
            s0 = fmaf(buf[cu][0].x, wv.x, s0); s0 = fmaf(buf[cu][0].y, wv.y, s0);
            s0 = fmaf(buf[cu][0].z, wv.z, s0); s0 = fmaf(buf[cu][0].w, wv.w, s0);
            s1 = fmaf(buf[cu][1].x, wv.x, s1); s1 = fmaf(buf[cu][1].y, wv.y, s1);
            s1 = fmaf(buf[cu][1].z, wv.z, s1); s1 = fmaf(buf[cu][1].w, wv.w, s1);
            s2 = fmaf(buf[cu][2].x, wv.x, s2); s2 = fmaf(buf[cu][2].y, wv.y, s2);
            s2 = fmaf(buf[cu][2].z, wv.z, s2); s2 = fmaf(buf[cu][2].w, wv.w, s2);
            s3 = fmaf(buf[cu][3].x, wv.x, s3); s3 = fmaf(buf[cu][3].y, wv.y, s3);
            s3 = fmaf(buf[cu][3].z, wv.z, s3); s3 = fmaf(buf[cu][3].w, wv.w, s3);
        }

        // 4 interleaved butterfly all-reduces.
        #pragma unroll
        for (int o = 16; o > 0; o >>= 1) {
            s0 += __shfl_xor_sync(0xFFFFFFFFu, s0, o);
            s1 += __shfl_xor_sync(0xFFFFFFFFu, s1, o);
            s2 += __shfl_xor_sync(0xFFFFFFFFu, s2, o);
            s3 += __shfl_xor_sync(0xFFFFFFFFu, s3, o);
        }

        // Epilogue: lanes 0..3 compute the 4 row GELUs in parallel.
        float v = -INFINITY;
        if (lane < 4) {
            float sum = (lane == 0) ? s0 : (lane == 1) ? s1 : (lane == 2) ? s2 : s3;
            float p = (sum + b) * 0.25f;
            float inner = 0.7978845608f * (p + 0.044715f * p * p * p);
            float g = 0.5f * p * (1.0f + tanhf(inner));
            v = g * 2.0f;
        }
        // chunk max -> lane 0
        v = fmaxf(v, __shfl_xor_sync(0xFFFFFFFFu, v, 1));
        v = fmaxf(v, __shfl_xor_sync(0xFFFFFFFFu, v, 2));

        // Zero-fill: rows row0..row0+3 form one 16B-aligned float4.
        // Non-head chunk: single vectorized zero store from lane 0.
        // Head chunk: lanes 1..3 store scalar zeros (head element untouched;
        // it is written only via atomics against the -inf init).
        const bool headChunk = (row0 & (GROUP - 1)) == 0;
        if (!headChunk) {
            if (lane == 0) {
                float4 z = make_float4(0.f, 0.f, 0.f, 0.f);
                *reinterpret_cast<float4*>(out + row0) = z;
            }
        } else {
            if (lane >= 1 && lane < 4) out[row0 + lane] = 0.0f;
        }

        if (lane == 0) {
            atomicMaxFloat(&out[row0 & ~(GROUP - 1)], v);
        }
    }
}

extern "C" void kernel_launch(void* const* d_in, const int* in_sizes, int n_in,
                              void* d_out, int out_size)
{
    const float* x    = (const float*)d_in[0];   // [65536, 2048]
    const float* w    = (const float*)d_in[1];   // [1, 2048]
    const float* bias = (const float*)d_in[2];   // [1]
    float* out = (float*)d_out;                  // [65536]

    init_heads<<<1, NGROUPS>>>(out);
    gemv_phase1<<<NSM, 1024>>>(x, w, bias, out);
}